// round 13
// baseline (speedup 1.0000x reference)
#include <cuda_runtime.h>

// SNN forward: T=1000, B=8192, I=9, H=96, O=3
// 4 batches/warp (2 independent batch-sets), CTA=128 (4 warps) so warps land on
// ALL FOUR SMSPs (wid%4) — 64-thread CTAs stranded SMSP 2/3. grid=512 -> 1 wave.
// v = beta*mem1 + b1 - spk1 fusion; FSET spikes; reduction split across iters.
// x pipeline depth 2: 4-buffer smem ring + two in-flight LDG registers.

#define T_STEPS 1000
#define BATCHN  8192
#define BETA    0.92f

typedef unsigned long long u64;

static __device__ __forceinline__ u64 pk2(float lo, float hi) {
    u64 r; asm("mov.b64 %0,{%1,%2};" : "=l"(r) : "f"(lo), "f"(hi)); return r;
}
static __device__ __forceinline__ void upk2(u64 v, float& a, float& b) {
    asm("mov.b64 {%0,%1},%2;" : "=f"(a), "=f"(b) : "l"(v));
}
static __device__ __forceinline__ u64 ffma2(u64 a, u64 b, u64 c) {
    u64 d; asm("fma.rn.f32x2 %0,%1,%2,%3;" : "=l"(d) : "l"(a), "l"(b), "l"(c)); return d;
}
static __device__ __forceinline__ u64 fmul2(u64 a, u64 b) {
    u64 d; asm("mul.rn.f32x2 %0,%1,%2;" : "=l"(d) : "l"(a), "l"(b)); return d;
}
static __device__ __forceinline__ float setgt1(float a) {
    float d; asm("set.gt.f32.f32 %0,%1,%2;" : "=f"(d) : "f"(a), "f"(1.0f)); return d;
}

__global__ void __launch_bounds__(128, 4) snn_kernel(
    const float* __restrict__ x,
    const float* __restrict__ W1,
    const float* __restrict__ b1,
    const float* __restrict__ W2,
    const float* __restrict__ b2,
    float* __restrict__ out)
{
    const int lane = threadIdx.x & 31;
    const int warp = threadIdx.x >> 5;           // 0..3 -> SMSP 0..3
    const int gw   = blockIdx.x * 4 + warp;
    const int grp  = lane >> 4;
    const int hl   = lane & 15;
    const int hb   = hl * 6;
    const int bA   = gw * 4 + grp;               // set-0 batch; set-1 = bA + 2

    // x ring: [warp][4 bufs][4 slots x 10 u64]
    __shared__ __align__(16) u64 xs[4][4][40];

    u64 w1p[3][9];
    #pragma unroll
    for (int j = 0; j < 3; j++)
        #pragma unroll
        for (int i = 0; i < 9; i++)
            w1p[j][i] = pk2(W1[(hb + 2*j) * 9 + i], W1[(hb + 2*j + 1) * 9 + i]);

    u64 w2p[3][3];
    #pragma unroll
    for (int o = 0; o < 3; o++)
        #pragma unroll
        for (int j = 0; j < 3; j++)
            w2p[o][j] = pk2(W2[o * 96 + hb + 2*j], W2[o * 96 + hb + 2*j + 1]);

    u64 b1p[3];
    #pragma unroll
    for (int j = 0; j < 3; j++) b1p[j] = pk2(b1[hb + 2*j], b1[hb + 2*j + 1]);

    const u64 BET2 = pk2(BETA, BETA);
    const u64 NEG1 = pk2(-1.0f, -1.0f);

    const int  oc        = (hl >> 2) > 2 ? 2 : (hl >> 2);
    const bool fin_store = ((hl & 3) < 2) && (hl < 12);
    const bool is_spk    = (hl & 3) == 0;
    const float bias     = b2[oc];

    float* optr = (is_spk ? out : out + (size_t)T_STEPS * BATCHN * 3)
                  + (size_t)bA * 3 + oc;

    u64 vA0 = b1p[0], vA1 = b1p[1], vA2 = b1p[2];
    u64 vB0 = b1p[0], vB1 = b1p[1], vB2 = b1p[2];
    float m2A = 0.f, spA = 0.f, ppA = 0.f;
    float m2B = 0.f, spB = 0.f, ppB = 0.f;

    // ---- x loaders: 36 contiguous floats per warp-step ----
    const int  idx0 = lane;
    const int  off0 = (idx0 / 9) * 10 + idx0 % 9;
    const bool l2   = lane < 4;
    const int  idx1 = 32 + lane;
    const int  off1 = (idx1 / 9) * 10 + idx1 % 9;
    const float* p0 = x + (size_t)gw * 36 + idx0;
    const float* p1 = x + (size_t)gw * 36 + idx1;
    const size_t xstr = (size_t)BATCHN * 9;

    // prologue: buffers 0,1 filled directly; x(2),x(3) in flight in registers
    {
        float v0l = p0[0];
        xs[warp][0][off0] = pk2(v0l, v0l);
        float v1l = p0[xstr];
        xs[warp][1][off0] = pk2(v1l, v1l);
        if (l2) {
            float w0l = p1[0];
            xs[warp][0][off1] = pk2(w0l, w0l);
            float w1l = p1[xstr];
            xs[warp][1][off1] = pk2(w1l, w1l);
        }
    }
    float rEa = p0[2 * xstr];
    float rEb = l2 ? p1[2 * xstr] : 0.f;
    float rOa = p0[3 * xstr];
    float rOb = l2 ? p1[3 * xstr] : 0.f;
    __syncwarp();

    #pragma unroll 2
    for (int t = 0; t < T_STEPS; t++) {
        u64* base  = xs[warp][t & 3];
        u64* stage = xs[warp][(t + 2) & 3];

        // ---- stage x(t+2) from the register loaded 2 iters ago; refill x(t+4) ----
        {
            float ra = (t & 1) ? rOa : rEa;
            float rb = (t & 1) ? rOb : rEb;
            stage[off0] = pk2(ra, ra);
            if (l2) stage[off1] = pk2(rb, rb);
            int tn = (t + 4 < T_STEPS) ? (t + 4) : (T_STEPS - 1);
            float na = p0[(size_t)tn * xstr];
            float nb = l2 ? p1[(size_t)tn * xstr] : 0.f;
            if (t & 1) { rOa = na; rOb = nb; } else { rEa = na; rEb = nb; }
        }

        // ---- head: finish previous step's reductions + finalize + store ----
        if (t) {
            float svA = ppA, svB = ppB;
            svA += __shfl_xor_sync(0xffffffffu, svA, 2);
            svB += __shfl_xor_sync(0xffffffffu, svB, 2);
            svA += __shfl_xor_sync(0xffffffffu, svA, 1);
            svB += __shfl_xor_sync(0xffffffffu, svB, 1);
            float mmA = fmaf(BETA, m2A, bias + svA) - spA;  m2A = mmA;
            float mmB = fmaf(BETA, m2B, bias + svB) - spB;  m2B = mmB;
            spA = setgt1(mmA);
            spB = setgt1(mmB);
            if (fin_store) {
                __stcs(optr,     is_spk ? spA : mmA);
                __stcs(optr + 6, is_spk ? spB : mmB);
            }
            optr += 3 * BATCHN;
        }
        __syncwarp();

        float sA0, sA1, sA2, sB0, sB1, sB2;

        // ======== batch set A ========
        {
            u64 xp[9];
            {
                const ulonglong2* q = reinterpret_cast<const ulonglong2*>(base + grp * 10);
                ulonglong2 t0 = q[0], t1 = q[1], t2 = q[2], t3 = q[3];
                xp[0] = t0.x; xp[1] = t0.y;
                xp[2] = t1.x; xp[3] = t1.y;
                xp[4] = t2.x; xp[5] = t2.y;
                xp[6] = t3.x; xp[7] = t3.y;
                xp[8] = base[grp * 10 + 8];
            }
            u64 a0 = vA0, a1 = vA1, a2 = vA2;
            #pragma unroll
            for (int i = 0; i < 9; i++) {
                a0 = ffma2(w1p[0][i], xp[i], a0);
                a1 = ffma2(w1p[1][i], xp[i], a1);
                a2 = ffma2(w1p[2][i], xp[i], a2);
            }
            float f0, f1;
            upk2(a0, f0, f1);
            u64 s0 = pk2(setgt1(f0), setgt1(f1));
            upk2(a1, f0, f1);
            u64 s1 = pk2(setgt1(f0), setgt1(f1));
            upk2(a2, f0, f1);
            u64 s2 = pk2(setgt1(f0), setgt1(f1));
            vA0 = ffma2(BET2, a0, ffma2(s0, NEG1, b1p[0]));
            vA1 = ffma2(BET2, a1, ffma2(s1, NEG1, b1p[1]));
            vA2 = ffma2(BET2, a2, ffma2(s2, NEG1, b1p[2]));

            u64 c0 = fmul2(s0, w2p[0][0]); c0 = ffma2(s1, w2p[0][1], c0); c0 = ffma2(s2, w2p[0][2], c0);
            u64 c1 = fmul2(s0, w2p[1][0]); c1 = ffma2(s1, w2p[1][1], c1); c1 = ffma2(s2, w2p[1][2], c1);
            u64 c2 = fmul2(s0, w2p[2][0]); c2 = ffma2(s1, w2p[2][1], c2); c2 = ffma2(s2, w2p[2][2], c2);
            float ta, tb;
            upk2(c0, ta, tb); sA0 = ta + tb;
            upk2(c1, ta, tb); sA1 = ta + tb;
            upk2(c2, ta, tb); sA2 = ta + tb;
        }

        // ======== batch set B ========
        {
            u64 xp[9];
            {
                const ulonglong2* q = reinterpret_cast<const ulonglong2*>(base + (grp + 2) * 10);
                ulonglong2 t0 = q[0], t1 = q[1], t2 = q[2], t3 = q[3];
                xp[0] = t0.x; xp[1] = t0.y;
                xp[2] = t1.x; xp[3] = t1.y;
                xp[4] = t2.x; xp[5] = t2.y;
                xp[6] = t3.x; xp[7] = t3.y;
                xp[8] = base[(grp + 2) * 10 + 8];
            }
            u64 a0 = vB0, a1 = vB1, a2 = vB2;
            #pragma unroll
            for (int i = 0; i < 9; i++) {
                a0 = ffma2(w1p[0][i], xp[i], a0);
                a1 = ffma2(w1p[1][i], xp[i], a1);
                a2 = ffma2(w1p[2][i], xp[i], a2);
            }
            float f0, f1;
            upk2(a0, f0, f1);
            u64 s0 = pk2(setgt1(f0), setgt1(f1));
            upk2(a1, f0, f1);
            u64 s1 = pk2(setgt1(f0), setgt1(f1));
            upk2(a2, f0, f1);
            u64 s2 = pk2(setgt1(f0), setgt1(f1));
            vB0 = ffma2(BET2, a0, ffma2(s0, NEG1, b1p[0]));
            vB1 = ffma2(BET2, a1, ffma2(s1, NEG1, b1p[1]));
            vB2 = ffma2(BET2, a2, ffma2(s2, NEG1, b1p[2]));

            u64 c0 = fmul2(s0, w2p[0][0]); c0 = ffma2(s1, w2p[0][1], c0); c0 = ffma2(s2, w2p[0][2], c0);
            u64 c1 = fmul2(s0, w2p[1][0]); c1 = ffma2(s1, w2p[1][1], c1); c1 = ffma2(s2, w2p[1][2], c1);
            u64 c2 = fmul2(s0, w2p[2][0]); c2 = ffma2(s1, w2p[2][1], c2); c2 = ffma2(s2, w2p[2][2], c2);
            float ta, tb;
            upk2(c0, ta, tb); sB0 = ta + tb;
            upk2(c1, ta, tb); sB1 = ta + tb;
            upk2(c2, ta, tb); sB2 = ta + tb;
        }

        // ---- tails interleaved: xor8 then xor4 ----
        sA0 += __shfl_xor_sync(0xffffffffu, sA0, 8);
        sA1 += __shfl_xor_sync(0xffffffffu, sA1, 8);
        sA2 += __shfl_xor_sync(0xffffffffu, sA2, 8);
        sB0 += __shfl_xor_sync(0xffffffffu, sB0, 8);
        sB1 += __shfl_xor_sync(0xffffffffu, sB1, 8);
        sB2 += __shfl_xor_sync(0xffffffffu, sB2, 8);
        sA0 += __shfl_xor_sync(0xffffffffu, sA0, 4);
        sA1 += __shfl_xor_sync(0xffffffffu, sA1, 4);
        sA2 += __shfl_xor_sync(0xffffffffu, sA2, 4);
        sB0 += __shfl_xor_sync(0xffffffffu, sB0, 4);
        sB1 += __shfl_xor_sync(0xffffffffu, sB1, 4);
        sB2 += __shfl_xor_sync(0xffffffffu, sB2, 4);
        ppA = (oc == 0) ? sA0 : ((oc == 1) ? sA1 : sA2);
        ppB = (oc == 0) ? sB0 : ((oc == 1) ? sB1 : sB2);
    }

    // ---- epilogue: timestep T-1 ----
    {
        float svA = ppA, svB = ppB;
        svA += __shfl_xor_sync(0xffffffffu, svA, 2);
        svB += __shfl_xor_sync(0xffffffffu, svB, 2);
        svA += __shfl_xor_sync(0xffffffffu, svA, 1);
        svB += __shfl_xor_sync(0xffffffffu, svB, 1);
        float mmA = fmaf(BETA, m2A, bias + svA) - spA;
        float mmB = fmaf(BETA, m2B, bias + svB) - spB;
        if (fin_store) {
            __stcs(optr,     is_spk ? setgt1(mmA) : mmA);
            __stcs(optr + 6, is_spk ? setgt1(mmB) : mmB);
        }
    }
}

extern "C" void kernel_launch(void* const* d_in, const int* in_sizes, int n_in,
                              void* d_out, int out_size) {
    const float* x  = (const float*)d_in[0];
    const float* W1 = (const float*)d_in[1];
    const float* b1 = (const float*)d_in[2];
    const float* W2 = (const float*)d_in[3];
    const float* b2 = (const float*)d_in[4];
    float* out = (float*)d_out;

    // 8192 batches / (4 per warp * 4 warps) = 512 CTAs of 128 threads.
    // 4 CTAs/SM * 148 SMs = 592 >= 512 -> single wave, all 4 SMSPs populated.
    snn_kernel<<<512, 128>>>(x, W1, b1, W2, b2, out);
}

// round 14
// speedup vs baseline: 1.0481x; 1.0481x over previous
#include <cuda_runtime.h>

// SNN forward: T=1000, B=8192, I=9, H=96, O=3
// 4 batches/warp (2 sets A/B), CTA=128 (4 warps), grid=512 -> single wave.
// v = beta*mem1 + b1 - spk1 fusion; FSET spikes; x pipeline depth 2 (4-buf ring).
// NEW: packed (A,B) reduction + finalize (f32x2 over the two batch sets),
//      peeled t=0 (unconditional head), unroll 4 for static ring indices.

#define T_STEPS 1000
#define BATCHN  8192
#define BETA    0.92f

typedef unsigned long long u64;

static __device__ __forceinline__ u64 pk2(float lo, float hi) {
    u64 r; asm("mov.b64 %0,{%1,%2};" : "=l"(r) : "f"(lo), "f"(hi)); return r;
}
static __device__ __forceinline__ void upk2(u64 v, float& a, float& b) {
    asm("mov.b64 {%0,%1},%2;" : "=f"(a), "=f"(b) : "l"(v));
}
static __device__ __forceinline__ u64 ffma2(u64 a, u64 b, u64 c) {
    u64 d; asm("fma.rn.f32x2 %0,%1,%2,%3;" : "=l"(d) : "l"(a), "l"(b), "l"(c)); return d;
}
static __device__ __forceinline__ u64 fadd2(u64 a, u64 b) {
    u64 d; asm("add.rn.f32x2 %0,%1,%2;" : "=l"(d) : "l"(a), "l"(b)); return d;
}
static __device__ __forceinline__ u64 fmul2(u64 a, u64 b) {
    u64 d; asm("mul.rn.f32x2 %0,%1,%2;" : "=l"(d) : "l"(a), "l"(b)); return d;
}
static __device__ __forceinline__ float setgt1(float a) {
    float d; asm("set.gt.f32.f32 %0,%1,%2;" : "=f"(d) : "f"(a), "f"(1.0f)); return d;
}
static __device__ __forceinline__ u64 shflx64(u64 v, int m) {
    unsigned lo = (unsigned)v;
    unsigned hi = (unsigned)(v >> 32);
    lo = __shfl_xor_sync(0xffffffffu, lo, m);
    hi = __shfl_xor_sync(0xffffffffu, hi, m);
    return ((u64)hi << 32) | lo;
}

__global__ void __launch_bounds__(128, 4) snn_kernel(
    const float* __restrict__ x,
    const float* __restrict__ W1,
    const float* __restrict__ b1,
    const float* __restrict__ W2,
    const float* __restrict__ b2,
    float* __restrict__ out)
{
    const int lane = threadIdx.x & 31;
    const int warp = threadIdx.x >> 5;
    const int gw   = blockIdx.x * 4 + warp;
    const int grp  = lane >> 4;
    const int hl   = lane & 15;
    const int hb   = hl * 6;
    const int bA   = gw * 4 + grp;               // set-A batch; set-B = bA + 2

    // x ring: [warp][4 bufs][4 slots x 10 u64]
    __shared__ __align__(16) u64 xs[4][4][40];

    u64 w1p[3][9];
    #pragma unroll
    for (int j = 0; j < 3; j++)
        #pragma unroll
        for (int i = 0; i < 9; i++)
            w1p[j][i] = pk2(W1[(hb + 2*j) * 9 + i], W1[(hb + 2*j + 1) * 9 + i]);

    u64 w2p[3][3];
    #pragma unroll
    for (int o = 0; o < 3; o++)
        #pragma unroll
        for (int j = 0; j < 3; j++)
            w2p[o][j] = pk2(W2[o * 96 + hb + 2*j], W2[o * 96 + hb + 2*j + 1]);

    u64 b1p[3];
    #pragma unroll
    for (int j = 0; j < 3; j++) b1p[j] = pk2(b1[hb + 2*j], b1[hb + 2*j + 1]);

    const u64 BET2 = pk2(BETA, BETA);
    const u64 NEG1 = pk2(-1.0f, -1.0f);

    const int  oc        = (hl >> 2) > 2 ? 2 : (hl >> 2);
    const bool fin_store = ((hl & 3) < 2) && (hl < 12);
    const bool is_spk    = (hl & 3) == 0;
    const u64  BIAS2     = pk2(b2[oc], b2[oc]);

    float* optr = (is_spk ? out : out + (size_t)T_STEPS * BATCHN * 3)
                  + (size_t)bA * 3 + oc;

    u64 vA0 = b1p[0], vA1 = b1p[1], vA2 = b1p[2];
    u64 vB0 = b1p[0], vB1 = b1p[1], vB2 = b1p[2];
    u64 m2 = 0ull, sp2 = 0ull, pp = 0ull;        // packed (A,B) layer-2 state

    // ---- x loaders: 36 contiguous floats per warp-step ----
    const int  idx0 = lane;
    const int  off0 = (idx0 / 9) * 10 + idx0 % 9;
    const bool l2   = lane < 4;
    const int  idx1 = 32 + lane;
    const int  off1 = (idx1 / 9) * 10 + idx1 % 9;
    const float* p0 = x + (size_t)gw * 36 + idx0;
    const float* p1 = x + (size_t)gw * 36 + idx1;
    const size_t xstr = (size_t)BATCHN * 9;

    // prologue: buffers 0,1 filled; x(2),x(3) in flight in registers
    {
        float v0l = p0[0];
        xs[warp][0][off0] = pk2(v0l, v0l);
        float v1l = p0[xstr];
        xs[warp][1][off0] = pk2(v1l, v1l);
        if (l2) {
            float w0l = p1[0];
            xs[warp][0][off1] = pk2(w0l, w0l);
            float w1l = p1[xstr];
            xs[warp][1][off1] = pk2(w1l, w1l);
        }
    }
    float rEa = p0[2 * xstr];
    float rEb = l2 ? p1[2 * xstr] : 0.f;
    float rOa = p0[3 * xstr];
    float rOb = l2 ? p1[3 * xstr] : 0.f;
    __syncwarp();

    // ===================== shared body pieces as macros =====================
#define LOAD_XP(xp, slot, buf)                                                  \
    {                                                                           \
        const ulonglong2* q = reinterpret_cast<const ulonglong2*>((buf) + (slot) * 10); \
        ulonglong2 q0 = q[0], q1 = q[1], q2 = q[2], q3 = q[3];                  \
        xp[0] = q0.x; xp[1] = q0.y; xp[2] = q1.x; xp[3] = q1.y;                 \
        xp[4] = q2.x; xp[5] = q2.y; xp[6] = q3.x; xp[7] = q3.y;                 \
        xp[8] = (buf)[(slot) * 10 + 8];                                         \
    }

#define SET_COMPUTE(xp, v0, v1, v2, s_0, s_1, s_2)                              \
    {                                                                           \
        u64 a0 = v0, a1 = v1, a2 = v2;                                          \
        _Pragma("unroll")                                                       \
        for (int i = 0; i < 9; i++) {                                           \
            a0 = ffma2(w1p[0][i], xp[i], a0);                                   \
            a1 = ffma2(w1p[1][i], xp[i], a1);                                   \
            a2 = ffma2(w1p[2][i], xp[i], a2);                                   \
        }                                                                       \
        float f0, f1;                                                           \
        upk2(a0, f0, f1);                                                       \
        u64 s0 = pk2(setgt1(f0), setgt1(f1));                                   \
        upk2(a1, f0, f1);                                                       \
        u64 s1 = pk2(setgt1(f0), setgt1(f1));                                   \
        upk2(a2, f0, f1);                                                       \
        u64 s2 = pk2(setgt1(f0), setgt1(f1));                                   \
        v0 = ffma2(BET2, a0, ffma2(s0, NEG1, b1p[0]));                          \
        v1 = ffma2(BET2, a1, ffma2(s1, NEG1, b1p[1]));                          \
        v2 = ffma2(BET2, a2, ffma2(s2, NEG1, b1p[2]));                          \
        u64 c0 = fmul2(s0, w2p[0][0]); c0 = ffma2(s1, w2p[0][1], c0); c0 = ffma2(s2, w2p[0][2], c0); \
        u64 c1 = fmul2(s0, w2p[1][0]); c1 = ffma2(s1, w2p[1][1], c1); c1 = ffma2(s2, w2p[1][2], c1); \
        u64 c2 = fmul2(s0, w2p[2][0]); c2 = ffma2(s1, w2p[2][1], c2); c2 = ffma2(s2, w2p[2][2], c2); \
        float ta, tb;                                                           \
        upk2(c0, ta, tb); s_0 = ta + tb;                                        \
        upk2(c1, ta, tb); s_1 = ta + tb;                                        \
        upk2(c2, ta, tb); s_2 = ta + tb;                                        \
    }

#define STAGE_PREFETCH(t)                                                       \
    {                                                                           \
        float ra = ((t) & 1) ? rOa : rEa;                                       \
        float rb = ((t) & 1) ? rOb : rEb;                                       \
        u64* stg = xs[warp][((t) + 2) & 3];                                     \
        stg[off0] = pk2(ra, ra);                                                \
        if (l2) stg[off1] = pk2(rb, rb);                                        \
        int tn = ((t) + 4 < T_STEPS) ? ((t) + 4) : (T_STEPS - 1);               \
        float na = p0[(size_t)tn * xstr];                                       \
        float nb = l2 ? p1[(size_t)tn * xstr] : 0.f;                            \
        if ((t) & 1) { rOa = na; rOb = nb; } else { rEa = na; rEb = nb; }       \
    }

#define TAIL_REDUCE()                                                           \
    {                                                                           \
        u64 P0 = pk2(sA0, sB0);                                                 \
        u64 P1 = pk2(sA1, sB1);                                                 \
        u64 P2 = pk2(sA2, sB2);                                                 \
        P0 = fadd2(P0, shflx64(P0, 8));                                         \
        P1 = fadd2(P1, shflx64(P1, 8));                                         \
        P2 = fadd2(P2, shflx64(P2, 8));                                         \
        P0 = fadd2(P0, shflx64(P0, 4));                                         \
        P1 = fadd2(P1, shflx64(P1, 4));                                         \
        P2 = fadd2(P2, shflx64(P2, 4));                                         \
        pp = (oc == 0) ? P0 : ((oc == 1) ? P1 : P2);                            \
    }

    // ---- peeled body t = 0 (no head) ----
    {
        u64 xpA[9];
        LOAD_XP(xpA, grp, xs[warp][0]);
        STAGE_PREFETCH(0);
        __syncwarp();
        float sA0, sA1, sA2, sB0, sB1, sB2;
        SET_COMPUTE(xpA, vA0, vA1, vA2, sA0, sA1, sA2);
        {
            u64 xpB[9];
            LOAD_XP(xpB, grp + 2, xs[warp][0]);
            SET_COMPUTE(xpB, vB0, vB1, vB2, sB0, sB1, sB2);
        }
        TAIL_REDUCE();
    }

    #pragma unroll 4
    for (int t = 1; t < T_STEPS; t++) {
        u64* base = xs[warp][t & 3];

        u64 xpA[9];
        LOAD_XP(xpA, grp, base);

        STAGE_PREFETCH(t);

        // ---- head: finish step t-1 (packed over A,B) ----
        {
            u64 sv = fadd2(pp, shflx64(pp, 2));
            sv = fadd2(sv, shflx64(sv, 1));
            u64 mm = ffma2(sp2, NEG1, ffma2(BET2, m2, fadd2(BIAS2, sv)));
            m2 = mm;
            float mmA, mmB;
            upk2(mm, mmA, mmB);
            float sa = setgt1(mmA), sb = setgt1(mmB);
            sp2 = pk2(sa, sb);
            if (fin_store) {
                __stcs(optr,     is_spk ? sa : mmA);
                __stcs(optr + 6, is_spk ? sb : mmB);
            }
            optr += 3 * BATCHN;
        }
        __syncwarp();

        float sA0, sA1, sA2, sB0, sB1, sB2;
        SET_COMPUTE(xpA, vA0, vA1, vA2, sA0, sA1, sA2);
        {
            u64 xpB[9];
            LOAD_XP(xpB, grp + 2, base);
            SET_COMPUTE(xpB, vB0, vB1, vB2, sB0, sB1, sB2);
        }
        TAIL_REDUCE();
    }

    // ---- epilogue: finalize timestep T-1 ----
    {
        u64 sv = fadd2(pp, shflx64(pp, 2));
        sv = fadd2(sv, shflx64(sv, 1));
        u64 mm = ffma2(sp2, NEG1, ffma2(BET2, m2, fadd2(BIAS2, sv)));
        float mmA, mmB;
        upk2(mm, mmA, mmB);
        if (fin_store) {
            __stcs(optr,     is_spk ? setgt1(mmA) : mmA);
            __stcs(optr + 6, is_spk ? setgt1(mmB) : mmB);
        }
    }

#undef LOAD_XP
#undef SET_COMPUTE
#undef STAGE_PREFETCH
#undef TAIL_REDUCE
}

extern "C" void kernel_launch(void* const* d_in, const int* in_sizes, int n_in,
                              void* d_out, int out_size) {
    const float* x  = (const float*)d_in[0];
    const float* W1 = (const float*)d_in[1];
    const float* b1 = (const float*)d_in[2];
    const float* W2 = (const float*)d_in[3];
    const float* b2 = (const float*)d_in[4];
    float* out = (float*)d_out;

    // 8192 batches / (4 per warp * 4 warps) = 512 CTAs of 128 threads -> 1 wave
    snn_kernel<<<512, 128>>>(x, W1, b1, W2, b2, out);
}